// round 7
// baseline (speedup 1.0000x reference)
#include <cuda_runtime.h>

// Fused: conv3d(16->32, k3, pad1) + bias + maxpool(2x2x2) + logsumexp(ch) + relu
// x: (16,16,32,64,64) f32, w: (32,16,3,3,3) f32, bias: (32) f32
// out: (16,1,16,32,32) f32
//
// Block = 256 threads = 16 oc-pairs x 16 pooled positions (tile 1x2x8 in od,oh,ow).
// Each thread computes channels (oc, oc+16) packed as f32x2, 8 conv accumulators
// (the 2x2x2 pool window). Weights live in smem as 8B (oc,oc+16) pairs; the x tile
// (all 16 input channels, with halo + zero padding) lives in smem.

#define TOH 2
#define TOW 8
#define SMEM_X_FLOATS (16 * 4 * 6 * 18)          // 6912 floats = 27648 B
#define SMEM_W_PAIRS  (16 * 27 * 16)             // 6912 ull    = 55296 B
#define SMEM_BYTES    (SMEM_X_FLOATS * 4 + SMEM_W_PAIRS * 8)  // 82944 B

__device__ __forceinline__ unsigned long long pack2(float v) {
    unsigned r = __float_as_uint(v);
    unsigned long long d;
    asm("mov.b64 %0, {%1, %1};" : "=l"(d) : "r"(r));
    return d;
}

__device__ __forceinline__ void fma2(unsigned long long& a,
                                     unsigned long long b,
                                     unsigned long long c) {
    // packed dual-fp32 FMA (Blackwell f32x2 pipe)
    asm("fma.rn.f32x2 %0, %1, %2, %3;" : "=l"(a) : "l"(b), "l"(c), "l"(a));
}

__global__ __launch_bounds__(256, 2)
void conv_pool_lse_kernel(const float* __restrict__ x,
                          const float* __restrict__ w,
                          const float* __restrict__ bias,
                          float* __restrict__ out) {
    extern __shared__ char smem[];
    float* xs = reinterpret_cast<float*>(smem);                               // [16][4][6][18]
    unsigned long long* ws =
        reinterpret_cast<unsigned long long*>(smem + SMEM_X_FLOATS * 4);      // [16][27][16]

    const int tid = threadIdx.x;
    const int bz = blockIdx.z;
    const int b  = bz >> 4;
    const int od = bz & 15;
    const int OH0 = blockIdx.y * TOH;
    const int OW0 = blockIdx.x * TOW;

    // ---- load weights into paired layout: ws[ic][tap][ocp] = (w[ocp], w[ocp+16]) ----
    {
        float* wsf = reinterpret_cast<float*>(ws);
        for (int j = tid; j < 13824; j += 256) {
            int ic  = j / 864;
            int r   = j - ic * 864;
            int tap = r >> 5;
            int r2  = r & 31;
            int ocp  = r2 >> 1;
            int half = r2 & 1;
            int oc = ocp + (half << 4);
            wsf[j] = w[oc * 432 + ic * 27 + tap];
        }
    }

    // ---- load x tile with halo + zero padding: xs[ic][xd][xh][xw], 4x6x18 per ic ----
    {
        const int d0 = od * 2 - 1;
        const int h0 = OH0 * 2 - 1;
        const int w0 = OW0 * 2 - 1;
        const float* xb = x + (long)b * (16 * 32 * 64 * 64);
        for (int i = tid; i < SMEM_X_FLOATS; i += 256) {
            int ic = i / 432;
            int r  = i - ic * 432;
            int xd = r / 108; r -= xd * 108;
            int xh = r / 18;
            int xw = r - xh * 18;
            int gd = d0 + xd, gh = h0 + xh, gw = w0 + xw;
            float v = 0.0f;
            if ((unsigned)gd < 32u && (unsigned)gh < 64u && (unsigned)gw < 64u)
                v = xb[((ic * 32 + gd) * 64 + gh) * 64 + gw];
            xs[i] = v;
        }
    }
    __syncthreads();

    // ---- main compute ----
    const int oc  = tid & 15;          // channel pair index: channels oc and oc+16
    const int pos = tid >> 4;          // 0..15 pooled positions
    const int ph  = pos >> 3;          // 0..1
    const int pw  = pos & 7;           // 0..7
    const int ch  = ph * 2;            // conv-row base within tile
    const int cw  = pw * 2;

    unsigned long long acc[2][2][2];
#pragma unroll
    for (int i = 0; i < 2; ++i)
#pragma unroll
        for (int j = 0; j < 2; ++j)
#pragma unroll
            for (int k = 0; k < 2; ++k) acc[i][j][k] = 0ull;

#pragma unroll 1
    for (int ic = 0; ic < 16; ++ic) {
        const float* xsl = xs + ic * 432;
        const unsigned long long* wl = ws + ic * (27 * 16) + oc;

#pragma unroll
        for (int xd = 0; xd < 4; ++xd) {
            // 4x4 patch of x at depth slice xd (broadcast loads: 2 addrs/warp)
            unsigned long long xp[16];
#pragma unroll
            for (int i = 0; i < 16; ++i)
                xp[i] = pack2(xsl[xd * 108 + (ch + (i >> 2)) * 18 + (cw + (i & 3))]);

#pragma unroll
            for (int dd = 0; dd < 2; ++dd) {
                const int kd = xd - dd;
                if (kd < 0 || kd > 2) continue;
#pragma unroll
                for (int kh = 0; kh < 3; ++kh) {
#pragma unroll
                    for (int kw = 0; kw < 3; ++kw) {
                        unsigned long long wp = wl[(kd * 9 + kh * 3 + kw) * 16];
                        fma2(acc[dd][0][0], wp, xp[(kh + 0) * 4 + kw + 0]);
                        fma2(acc[dd][0][1], wp, xp[(kh + 0) * 4 + kw + 1]);
                        fma2(acc[dd][1][0], wp, xp[(kh + 1) * 4 + kw + 0]);
                        fma2(acc[dd][1][1], wp, xp[(kh + 1) * 4 + kw + 1]);
                    }
                }
            }
        }
    }

    // ---- maxpool over the 2x2x2 accumulators, + bias ----
    float m0 = -3.0e38f, m1 = -3.0e38f;
#pragma unroll
    for (int i = 0; i < 2; ++i)
#pragma unroll
        for (int j = 0; j < 2; ++j)
#pragma unroll
            for (int k = 0; k < 2; ++k) {
                unsigned long long a = acc[i][j][k];
                m0 = fmaxf(m0, __uint_as_float((unsigned)a));
                m1 = fmaxf(m1, __uint_as_float((unsigned)(a >> 32)));
            }
    m0 += bias[oc];
    m1 += bias[oc + 16];

    // ---- logsumexp over 32 channels (16 lanes x 2 channels each) + relu ----
    // Lanes 0-15 and 16-31 of a warp are two independent pooled positions;
    // xor masks 8,4,2,1 stay inside each 16-lane group.
    float m = fmaxf(m0, m1);
#pragma unroll
    for (int msk = 8; msk; msk >>= 1)
        m = fmaxf(m, __shfl_xor_sync(0xffffffffu, m, msk));
    float s = expf(m0 - m) + expf(m1 - m);
#pragma unroll
    for (int msk = 8; msk; msk >>= 1)
        s += __shfl_xor_sync(0xffffffffu, s, msk);

    if (oc == 0) {
        float r = m + logf(s);
        out[((b * 16 + od) * 32 + (OH0 + ph)) * 32 + (OW0 + pw)] = fmaxf(r, 0.0f);
    }
}

extern "C" void kernel_launch(void* const* d_in, const int* in_sizes, int n_in,
                              void* d_out, int out_size) {
    (void)in_sizes; (void)n_in; (void)out_size;
    const float* x    = (const float*)d_in[0];
    const float* w    = (const float*)d_in[1];
    const float* bias = (const float*)d_in[2];
    float* out        = (float*)d_out;

    // Opt in to >48KB dynamic smem (idempotent; not a stream op, capture-legal).
    (void)cudaFuncSetAttribute(conv_pool_lse_kernel,
                               cudaFuncAttributeMaxDynamicSharedMemorySize, SMEM_BYTES);

    dim3 grid(32 / TOW, 32 / TOH, 16 * 16);   // (ow tiles, oh tiles, b*od)
    conv_pool_lse_kernel<<<grid, 256, SMEM_BYTES>>>(x, w, bias, out);
}